// round 11
// baseline (speedup 1.0000x reference)
#include <cuda_runtime.h>
#include <cstdint>

#define NN 100000
#define EE 800000
#define GG 64
#define HH 128
#define FIN 64
#define NBLK ((NN + 1023) / 1024)   // 98

// Scratch (__device__ globals; no allocation allowed)
__device__ __align__(16) float g_u[(size_t)NN * HH];
__device__ __align__(16) float g_z[(size_t)NN * HH];
__device__ float g_dinv[NN];
__device__ int   g_cnt[NN];
__device__ int   g_off[NN + 1];
__device__ int   g_cur[NN];
__device__ __align__(8) int2 g_csr2[EE];   // (src, bits(dinv[src]))
__device__ int   g_bsum[128];
__device__ __align__(16) float g_pool[GG * HH];

// ---------------------------------------------------------------------------
__device__ __forceinline__ void ffma2(unsigned long long& acc, unsigned long long a,
                                      unsigned long long b) {
    asm("fma.rn.f32x2 %0, %1, %2, %0;" : "+l"(acc) : "l"(a), "l"(b));
}
__device__ __forceinline__ float fsum2(unsigned long long v) {
    float lo, hi;
    asm("mov.b64 {%0,%1}, %2;" : "=f"(lo), "=f"(hi) : "l"(v));
    return lo + hi;
}

// ---------------------------------------------------------------------------
__global__ void init_kernel() {
    int i = blockIdx.x * blockDim.x + threadIdx.x;
    if (i < NN) g_cnt[i] = 0;
    if (i < GG * HH) g_pool[i] = 0.0f;
}
__global__ void hist_kernel(const int* __restrict__ ei) {
    int e = blockIdx.x * blockDim.x + threadIdx.x;
    if (e < EE) atomicAdd(&g_cnt[ei[EE + e]], 1);
}

// Block scan (1024/block) + dinv
__global__ void scan1_kernel() {
    __shared__ int ssum[256];
    const int tid = threadIdx.x;
    const int base = blockIdx.x * 1024 + tid * 4;
    int v[4];
#pragma unroll
    for (int j = 0; j < 4; j++) {
        int idx = base + j;
        v[j] = (idx < NN) ? g_cnt[idx] : 0;
        if (idx < NN) g_dinv[idx] = rsqrtf((float)v[j] + 1.0f);
    }
    int s = v[0] + v[1] + v[2] + v[3];
    ssum[tid] = s;
    __syncthreads();
    for (int d = 1; d < 256; d <<= 1) {
        int t = (tid >= d) ? ssum[tid - d] : 0;
        __syncthreads();
        ssum[tid] += t;
        __syncthreads();
    }
    int run = ssum[tid] - s;
#pragma unroll
    for (int j = 0; j < 4; j++) {
        int idx = base + j;
        if (idx < NN) g_off[idx] = run;
        run += v[j];
    }
    if (tid == 255) g_bsum[blockIdx.x] = ssum[255];
}

// scan3: scan2 folded in (each block redundantly scans the 98 block sums).
__global__ void scan3_kernel() {
    __shared__ int pre[128];
    const int tid = threadIdx.x;  // 256
    int v = 0;
    if (tid < 128) {
        v = (tid < NBLK) ? g_bsum[tid] : 0;
        pre[tid] = v;
    }
    __syncthreads();
    for (int d = 1; d < 128; d <<= 1) {
        int t = 0;
        if (tid < 128 && tid >= d) t = pre[tid - d];
        __syncthreads();
        if (tid < 128) pre[tid] += t;
        __syncthreads();
    }
    if (tid < 128) pre[tid] -= v;  // exclusive
    __syncthreads();
    int i = blockIdx.x * 256 + tid;
    if (i < NN) {
        int off = g_off[i] + pre[i >> 10];
        g_off[i] = off;
        g_cur[i] = off;
    }
    if (i == 0) g_off[NN] = EE;
}

// Scatter edges with precomputed source weight: one 8B payload per edge.
__global__ void scatter_kernel(const int* __restrict__ ei) {
    int e = blockIdx.x * blockDim.x + threadIdx.x;
    if (e >= EE) return;
    int src = ei[e];
    int dst = ei[EE + e];
    int pos = atomicAdd(&g_cur[dst], 1);
    g_csr2[pos] = make_int2(src, __float_as_int(g_dinv[src]));
}

// ---------------------------------------------------------------------------
// Aggregation u = A_hat * z (CSR, atomic-free). One int2 load per edge
// (index + weight), unroll-4 batched prefetch.
template <int DIM>
__global__ void agg_kernel(const float* __restrict__ z, float* __restrict__ u) {
    constexpr int GPN = DIM / 4;
    constexpr int SH = (DIM == 64) ? 4 : 5;
    const int gt = blockIdx.x * 256 + threadIdx.x;
    const int node = gt >> SH;
    if (node >= NN) return;
    const int q = gt & (GPN - 1);
    const float dd = g_dinv[node];
    const int s = g_off[node], e = g_off[node + 1];
    const float4* Z = (const float4*)z;
    float4 v0 = Z[(size_t)node * GPN + q];
    float ax = dd * v0.x, ay = dd * v0.y, az = dd * v0.z, aw = dd * v0.w;
    int i = s;
    for (; i + 4 <= e; i += 4) {
        int2 p0 = g_csr2[i], p1 = g_csr2[i + 1], p2 = g_csr2[i + 2], p3 = g_csr2[i + 3];
        float d0 = __int_as_float(p0.y), d1 = __int_as_float(p1.y);
        float d2 = __int_as_float(p2.y), d3 = __int_as_float(p3.y);
        float4 a = Z[(size_t)p0.x * GPN + q];
        float4 b = Z[(size_t)p1.x * GPN + q];
        float4 c = Z[(size_t)p2.x * GPN + q];
        float4 d4 = Z[(size_t)p3.x * GPN + q];
        ax += d0 * a.x + d1 * b.x + d2 * c.x + d3 * d4.x;
        ay += d0 * a.y + d1 * b.y + d2 * c.y + d3 * d4.y;
        az += d0 * a.z + d1 * b.z + d2 * c.z + d3 * d4.z;
        aw += d0 * a.w + d1 * b.w + d2 * c.w + d3 * d4.w;
    }
    for (; i < e; i++) {
        int2 p0 = g_csr2[i];
        float d0 = __int_as_float(p0.y);
        float4 a = Z[(size_t)p0.x * GPN + q];
        ax += d0 * a.x; ay += d0 * a.y; az += d0 * a.z; aw += d0 * a.w;
    }
    ((float4*)u)[(size_t)node * GPN + q] = make_float4(dd * ax, dd * ay, dd * az, dd * aw);
}

// ---------------------------------------------------------------------------
// FFMA2 GEMM (exact R9 proven config): Z[N,128] = act(A[N,K] @ W[K,128] + b).
// 256 threads, block tile 64x128, per-thread 8 rows x 4 cols, f32x2 k-pairs.
template <int K, bool RELU, bool POOL>
__global__ void __launch_bounds__(256) gemm_kernel(const float* __restrict__ A,
                                                   const float* __restrict__ W,
                                                   const float* __restrict__ bias,
                                                   float* __restrict__ Z,
                                                   const int* __restrict__ batch) {
    constexpr int KP = K + 4;
    extern __shared__ char smraw[];
    float* Ash = (float*)smraw;                       // [64][KP]
    float2* Wsh = (float2*)(smraw + 64 * KP * 4);     // [128 cols][17 k-pairs]
    const int tid = threadIdx.x;
    const int lane = tid & 31;
    const int rg = tid >> 5;
    const int blockRow = blockIdx.x * 64;

#pragma unroll
    for (int f4 = tid; f4 < 64 * (K / 4); f4 += 256) {
        int row = f4 / (K / 4);
        int q = f4 % (K / 4);
        int grow = blockRow + row;
        float4 v = (grow < NN) ? *(const float4*)(A + (size_t)grow * K + q * 4)
                               : make_float4(0.f, 0.f, 0.f, 0.f);
        *(float4*)(Ash + row * KP + 4 * q) = v;
    }

    unsigned long long acc2[8][4];
#pragma unroll
    for (int i = 0; i < 8; i++)
#pragma unroll
        for (int j = 0; j < 4; j++) acc2[i][j] = 0ull;

    for (int kc = 0; kc < K; kc += 32) {
        __syncthreads();
        {
            int c = tid & 127;
            int half = tid >> 7;
#pragma unroll
            for (int t = 0; t < 8; t++) {
                int k2 = half * 8 + t;
                float w0 = W[(size_t)(kc + 2 * k2) * HH + c];
                float w1 = W[(size_t)(kc + 2 * k2 + 1) * HH + c];
                Wsh[c * 17 + k2] = make_float2(w0, w1);
            }
        }
        __syncthreads();
#pragma unroll
        for (int k2 = 0; k2 < 16; k2++) {
            unsigned long long a2[8], w2[4];
#pragma unroll
            for (int i = 0; i < 8; i++)
                a2[i] = *(const unsigned long long*)(Ash + (rg * 8 + i) * KP + kc + 2 * k2);
#pragma unroll
            for (int j = 0; j < 4; j++)
                w2[j] = *(const unsigned long long*)(&Wsh[(lane + 32 * j) * 17 + k2]);
#pragma unroll
            for (int i = 0; i < 8; i++)
#pragma unroll
                for (int j = 0; j < 4; j++) ffma2(acc2[i][j], a2[i], w2[j]);
        }
    }

    float acc[8][4];
#pragma unroll
    for (int i = 0; i < 8; i++)
#pragma unroll
        for (int j = 0; j < 4; j++) acc[i][j] = fsum2(acc2[i][j]);

    if (!POOL) {
        float b[4];
#pragma unroll
        for (int j = 0; j < 4; j++) b[j] = bias[lane + 32 * j];
#pragma unroll
        for (int i = 0; i < 8; i++) {
            int grow = blockRow + rg * 8 + i;
            if (grow >= NN) continue;
            float* Zr = Z + (size_t)grow * HH;
#pragma unroll
            for (int j = 0; j < 4; j++) {
                float o = acc[i][j] + b[j];
                if (RELU) o = fmaxf(o, 0.f);
                Zr[lane + 32 * j] = o;
            }
        }
    } else {
        int i = 0;
        while (i < 8) {
            int grow = blockRow + rg * 8 + i;
            if (grow >= NN) break;
            int g = batch[grow];
            float s[4] = {acc[i][0], acc[i][1], acc[i][2], acc[i][3]};
            int i2 = i + 1;
            while (i2 < 8) {
                int gr2 = blockRow + rg * 8 + i2;
                if (gr2 >= NN || batch[gr2] != g) break;
#pragma unroll
                for (int j = 0; j < 4; j++) s[j] += acc[i2][j];
                i2++;
            }
            float* p = g_pool + g * HH;
#pragma unroll
            for (int j = 0; j < 4; j++)
                asm volatile("red.global.add.f32 [%0], %1;" ::"l"(p + lane + 32 * j),
                             "f"(s[j]) : "memory");
            i = i2;
        }
    }
}

// ---------------------------------------------------------------------------
// MLP head. Graph size via binary search on sorted batch (no atomics).
__global__ void mlp_kernel(const int* __restrict__ bat,
                           const float* __restrict__ b3,
                           const float* __restrict__ fw1, const float* __restrict__ fb1,
                           const float* __restrict__ fw2, const float* __restrict__ fb2,
                           float* __restrict__ out) {
    const int g = blockIdx.x;
    const int j = threadIdx.x;  // 128
    __shared__ float p[HH];
    __shared__ float z[HH];
    __shared__ int bounds[2];
    if (j < 2) {
        int key = g + j;
        int lo = 0, hi = NN;
        while (lo < hi) {
            int mid = (lo + hi) >> 1;
            if (bat[mid] < key) lo = mid + 1;
            else hi = mid;
        }
        bounds[j] = lo;
    }
    __syncthreads();
    const float c = fmaxf((float)(bounds[1] - bounds[0]), 1.0f);
    p[j] = g_pool[g * HH + j] / c + b3[j];
    __syncthreads();
    float acc = fb1[j];
#pragma unroll 8
    for (int k = 0; k < HH; k++) acc += p[k] * fw1[k * HH + j];
    z[j] = fmaxf(acc, 0.0f);
    __syncthreads();
    if (j < 4) {
        float o = fb2[j];
#pragma unroll 8
        for (int k = 0; k < HH; k++) o += z[k] * fw2[k * 4 + j];
        out[g * 4 + j] = o;
    }
}

// ---------------------------------------------------------------------------
extern "C" void kernel_launch(void* const* d_in, const int* in_sizes, int n_in,
                              void* d_out, int out_size) {
    const float* x   = (const float*)d_in[0];
    const float* W1  = (const float*)d_in[1];
    const float* b1  = (const float*)d_in[2];
    const float* W2  = (const float*)d_in[3];
    const float* b2  = (const float*)d_in[4];
    const float* W3  = (const float*)d_in[5];
    const float* b3  = (const float*)d_in[6];
    const float* fw1 = (const float*)d_in[7];
    const float* fb1 = (const float*)d_in[8];
    const float* fw2 = (const float*)d_in[9];
    const float* fb2 = (const float*)d_in[10];
    const int*   ei  = (const int*)d_in[11];
    const int*   bat = (const int*)d_in[12];
    float* out = (float*)d_out;

    float *du, *dz;
    cudaGetSymbolAddress((void**)&du, g_u);
    cudaGetSymbolAddress((void**)&dz, g_z);

    const int SMEM64 = 64 * (FIN + 4) * 4 + 128 * 17 * 8;   // 34816
    const int SMEM128 = 64 * (HH + 4) * 4 + 128 * 17 * 8;   // 51200
    cudaFuncSetAttribute(gemm_kernel<FIN, true, false>,
                         cudaFuncAttributeMaxDynamicSharedMemorySize, SMEM64);
    cudaFuncSetAttribute(gemm_kernel<HH, true, false>,
                         cudaFuncAttributeMaxDynamicSharedMemorySize, SMEM128);
    cudaFuncSetAttribute(gemm_kernel<HH, false, true>,
                         cudaFuncAttributeMaxDynamicSharedMemorySize, SMEM128);

    // --- CSR build (+ dinv) ---
    init_kernel<<<(NN + 255) / 256, 256>>>();
    hist_kernel<<<(EE + 255) / 256, 256>>>(ei);
    scan1_kernel<<<NBLK, 256>>>();
    scan3_kernel<<<(NN + 255) / 256, 256>>>();
    scatter_kernel<<<(EE + 255) / 256, 256>>>(ei);

    const int GEMM_GRID = (NN + 63) / 64;  // 1563

    // Layer 1
    agg_kernel<FIN><<<(NN * 16 + 255) / 256, 256>>>(x, du);
    gemm_kernel<FIN, true, false><<<GEMM_GRID, 256, SMEM64>>>(du, W1, b1, dz, nullptr);
    // Layer 2
    agg_kernel<HH><<<(NN * 32 + 255) / 256, 256>>>(dz, du);
    gemm_kernel<HH, true, false><<<GEMM_GRID, 256, SMEM128>>>(du, W2, b2, dz, nullptr);
    // Layer 3 -> pool directly
    agg_kernel<HH><<<(NN * 32 + 255) / 256, 256>>>(dz, du);
    gemm_kernel<HH, false, true><<<GEMM_GRID, 256, SMEM128>>>(du, W3, nullptr, nullptr, bat);

    mlp_kernel<<<GG, HH>>>(bat, b3, fw1, fb1, fw2, fb2, out);
}

// round 13
// speedup vs baseline: 1.2042x; 1.2042x over previous
#include <cuda_runtime.h>
#include <cstdint>

#define NN 100000
#define EE 800000
#define GG 64
#define HH 128
#define FIN 64
#define NBLK ((NN + 1023) / 1024)   // 98

// Scratch (__device__ globals; no allocation allowed)
__device__ __align__(16) float g_u[(size_t)NN * HH];
__device__ __align__(16) float g_z[(size_t)NN * HH];
__device__ float g_dinv[NN];
__device__ int   g_cnt[NN];
__device__ int   g_off[NN + 1];
__device__ int   g_cur[NN];
__device__ int   g_csr[EE];
__device__ int   g_bsum[128];

// ---------------------------------------------------------------------------
__device__ __forceinline__ void ffma2(unsigned long long& acc, unsigned long long a,
                                      unsigned long long b) {
    asm("fma.rn.f32x2 %0, %1, %2, %0;" : "+l"(acc) : "l"(a), "l"(b));
}
__device__ __forceinline__ float fsum2(unsigned long long v) {
    float lo, hi;
    asm("mov.b64 {%0,%1}, %2;" : "=f"(lo), "=f"(hi) : "l"(v));
    return lo + hi;
}

// ---------------------------------------------------------------------------
__global__ void init_kernel() {
    int i = blockIdx.x * blockDim.x + threadIdx.x;
    if (i < NN) g_cnt[i] = 0;
}
__global__ void hist_kernel(const int* __restrict__ ei) {
    int e = blockIdx.x * blockDim.x + threadIdx.x;
    if (e < EE) atomicAdd(&g_cnt[ei[EE + e]], 1);
}

// Block scan (1024/block) + dinv
__global__ void scan1_kernel() {
    __shared__ int ssum[256];
    const int tid = threadIdx.x;
    const int base = blockIdx.x * 1024 + tid * 4;
    int v[4];
#pragma unroll
    for (int j = 0; j < 4; j++) {
        int idx = base + j;
        v[j] = (idx < NN) ? g_cnt[idx] : 0;
        if (idx < NN) g_dinv[idx] = rsqrtf((float)v[j] + 1.0f);
    }
    int s = v[0] + v[1] + v[2] + v[3];
    ssum[tid] = s;
    __syncthreads();
    for (int d = 1; d < 256; d <<= 1) {
        int t = (tid >= d) ? ssum[tid - d] : 0;
        __syncthreads();
        ssum[tid] += t;
        __syncthreads();
    }
    int run = ssum[tid] - s;
#pragma unroll
    for (int j = 0; j < 4; j++) {
        int idx = base + j;
        if (idx < NN) g_off[idx] = run;
        run += v[j];
    }
    if (tid == 255) g_bsum[blockIdx.x] = ssum[255];
}

// scan3: scan2 folded in (each block redundantly scans the 98 block sums).
__global__ void scan3_kernel() {
    __shared__ int pre[128];
    const int tid = threadIdx.x;  // 256
    int v = 0;
    if (tid < 128) {
        v = (tid < NBLK) ? g_bsum[tid] : 0;
        pre[tid] = v;
    }
    __syncthreads();
    for (int d = 1; d < 128; d <<= 1) {
        int t = 0;
        if (tid < 128 && tid >= d) t = pre[tid - d];
        __syncthreads();
        if (tid < 128) pre[tid] += t;
        __syncthreads();
    }
    if (tid < 128) pre[tid] -= v;  // exclusive
    __syncthreads();
    int i = blockIdx.x * 256 + tid;
    if (i < NN) {
        int off = g_off[i] + pre[i >> 10];
        g_off[i] = off;
        g_cur[i] = off;
    }
    if (i == 0) g_off[NN] = EE;
}
__global__ void scatter_kernel(const int* __restrict__ ei) {
    int e = blockIdx.x * blockDim.x + threadIdx.x;
    if (e >= EE) return;
    int pos = atomicAdd(&g_cur[ei[EE + e]], 1);
    g_csr[pos] = ei[e];
}

// ---------------------------------------------------------------------------
// Aggregation u = A_hat * z (CSR, atomic-free). Unroll-4, batched prefetch.
template <int DIM>
__global__ void agg_kernel(const float* __restrict__ z, float* __restrict__ u) {
    constexpr int GPN = DIM / 4;
    constexpr int SH = (DIM == 64) ? 4 : 5;
    const int gt = blockIdx.x * 256 + threadIdx.x;
    const int node = gt >> SH;
    if (node >= NN) return;
    const int q = gt & (GPN - 1);
    const float dd = g_dinv[node];
    const int s = g_off[node], e = g_off[node + 1];
    const float4* Z = (const float4*)z;
    float4 v0 = Z[(size_t)node * GPN + q];
    float ax = dd * v0.x, ay = dd * v0.y, az = dd * v0.z, aw = dd * v0.w;
    int i = s;
    for (; i + 4 <= e; i += 4) {
        int s0 = g_csr[i], s1 = g_csr[i + 1], s2 = g_csr[i + 2], s3 = g_csr[i + 3];
        float d0 = g_dinv[s0], d1 = g_dinv[s1], d2 = g_dinv[s2], d3 = g_dinv[s3];
        float4 a = Z[(size_t)s0 * GPN + q];
        float4 b = Z[(size_t)s1 * GPN + q];
        float4 c = Z[(size_t)s2 * GPN + q];
        float4 d4 = Z[(size_t)s3 * GPN + q];
        ax += d0 * a.x + d1 * b.x + d2 * c.x + d3 * d4.x;
        ay += d0 * a.y + d1 * b.y + d2 * c.y + d3 * d4.y;
        az += d0 * a.z + d1 * b.z + d2 * c.z + d3 * d4.z;
        aw += d0 * a.w + d1 * b.w + d2 * c.w + d3 * d4.w;
    }
    for (; i < e; i++) {
        int s0 = g_csr[i];
        float d0 = g_dinv[s0];
        float4 a = Z[(size_t)s0 * GPN + q];
        ax += d0 * a.x; ay += d0 * a.y; az += d0 * a.z; aw += d0 * a.w;
    }
    ((float4*)u)[(size_t)node * GPN + q] = make_float4(dd * ax, dd * ay, dd * az, dd * aw);
}

// ---------------------------------------------------------------------------
// FFMA2 GEMM (proven R9 config): Z[N,128] = relu(A[N,K] @ W[K,128] + b).
// 256 threads, block tile 64x128, per-thread 8 rows x 4 cols, f32x2 k-pairs.
template <int K>
__global__ void __launch_bounds__(256) gemm_kernel(const float* __restrict__ A,
                                                   const float* __restrict__ W,
                                                   const float* __restrict__ bias,
                                                   float* __restrict__ Z) {
    constexpr int KP = K + 4;
    extern __shared__ char smraw[];
    float* Ash = (float*)smraw;                       // [64][KP]
    float2* Wsh = (float2*)(smraw + 64 * KP * 4);     // [128 cols][17 k-pairs]
    const int tid = threadIdx.x;
    const int lane = tid & 31;
    const int rg = tid >> 5;
    const int blockRow = blockIdx.x * 64;

#pragma unroll
    for (int f4 = tid; f4 < 64 * (K / 4); f4 += 256) {
        int row = f4 / (K / 4);
        int q = f4 % (K / 4);
        int grow = blockRow + row;
        float4 v = (grow < NN) ? *(const float4*)(A + (size_t)grow * K + q * 4)
                               : make_float4(0.f, 0.f, 0.f, 0.f);
        *(float4*)(Ash + row * KP + 4 * q) = v;
    }

    unsigned long long acc2[8][4];
#pragma unroll
    for (int i = 0; i < 8; i++)
#pragma unroll
        for (int j = 0; j < 4; j++) acc2[i][j] = 0ull;

    for (int kc = 0; kc < K; kc += 32) {
        __syncthreads();
        {
            int c = tid & 127;
            int half = tid >> 7;
#pragma unroll
            for (int t = 0; t < 8; t++) {
                int k2 = half * 8 + t;
                float w0 = W[(size_t)(kc + 2 * k2) * HH + c];
                float w1 = W[(size_t)(kc + 2 * k2 + 1) * HH + c];
                Wsh[c * 17 + k2] = make_float2(w0, w1);
            }
        }
        __syncthreads();
#pragma unroll
        for (int k2 = 0; k2 < 16; k2++) {
            unsigned long long a2[8], w2[4];
#pragma unroll
            for (int i = 0; i < 8; i++)
                a2[i] = *(const unsigned long long*)(Ash + (rg * 8 + i) * KP + kc + 2 * k2);
#pragma unroll
            for (int j = 0; j < 4; j++)
                w2[j] = *(const unsigned long long*)(&Wsh[(lane + 32 * j) * 17 + k2]);
#pragma unroll
            for (int i = 0; i < 8; i++)
#pragma unroll
                for (int j = 0; j < 4; j++) ffma2(acc2[i][j], a2[i], w2[j]);
        }
    }

    float b[4];
#pragma unroll
    for (int j = 0; j < 4; j++) b[j] = bias[lane + 32 * j];
#pragma unroll
    for (int i = 0; i < 8; i++) {
        int grow = blockRow + rg * 8 + i;
        if (grow >= NN) continue;
        float* Zr = Z + (size_t)grow * HH;
#pragma unroll
        for (int j = 0; j < 4; j++) {
            float o = fsum2(acc2[i][j]) + b[j];
            Zr[lane + 32 * j] = fmaxf(o, 0.f);
        }
    }
}

// ---------------------------------------------------------------------------
// Pool + MLP head, fused. Layer-3 GEMM eliminated algebraically:
//   pooled[g] = (segsum(u3) @ W3)/cnt + b3  (since segsum is linear in W3).
// Block g: binary-search row range, segment-sum u3 -> S (smem), tiny GEMM,
// then the 2-layer MLP. No atomics, no g_pool.
__global__ void pool_mlp_kernel(const int* __restrict__ bat,
                                const float* __restrict__ u3,
                                const float* __restrict__ W3,
                                const float* __restrict__ b3,
                                const float* __restrict__ fw1, const float* __restrict__ fb1,
                                const float* __restrict__ fw2, const float* __restrict__ fb2,
                                float* __restrict__ out) {
    const int g = blockIdx.x;
    const int tid = threadIdx.x;  // 256
    __shared__ int bounds[2];
    __shared__ __align__(16) float partial[8 * HH];   // [strip][col], 16B-aligned for float4
    __shared__ __align__(16) float S[HH];
    __shared__ __align__(16) float p[HH];
    __shared__ __align__(16) float z[HH];

    if (tid < 2) {
        int key = g + tid;
        int lo = 0, hi = NN;
        while (lo < hi) {
            int mid = (lo + hi) >> 1;
            if (bat[mid] < key) lo = mid + 1;
            else hi = mid;
        }
        bounds[tid] = lo;
    }
    __syncthreads();
    const int lo = bounds[0], hi = bounds[1];

    // Segment sum of u3 rows [lo, hi): 32 float4-cols x 8 row-strips.
    {
        const int q = tid & 31;
        const int strip = tid >> 5;
        float4 s = make_float4(0.f, 0.f, 0.f, 0.f);
        const float4* U = (const float4*)u3;
        for (int r = lo + strip; r < hi; r += 8) {
            float4 v = U[(size_t)r * 32 + q];
            s.x += v.x; s.y += v.y; s.z += v.z; s.w += v.w;
        }
        ((float4*)partial)[strip * 32 + q] = s;
    }
    __syncthreads();
    if (tid < HH) {
        float v = 0.f;
#pragma unroll
        for (int st = 0; st < 8; st++) v += partial[st * HH + tid];
        S[tid] = v;
    }
    __syncthreads();

    // p = (S @ W3)/cnt + b3 (empty graph -> 0, matching reference).
    if (tid < HH) {
        const int j = tid;
        float acc = 0.f;
#pragma unroll 8
        for (int k = 0; k < HH; k++) acc += S[k] * W3[k * HH + j];
        p[j] = (hi > lo) ? acc / (float)(hi - lo) + b3[j] : 0.0f;
    }
    __syncthreads();
    if (tid < HH) {
        const int j = tid;
        float acc = fb1[j];
#pragma unroll 8
        for (int k = 0; k < HH; k++) acc += p[k] * fw1[k * HH + j];
        z[j] = fmaxf(acc, 0.0f);
    }
    __syncthreads();
    if (tid < 4) {
        float o = fb2[tid];
#pragma unroll 8
        for (int k = 0; k < HH; k++) o += z[k] * fw2[k * 4 + tid];
        out[g * 4 + tid] = o;
    }
}

// ---------------------------------------------------------------------------
extern "C" void kernel_launch(void* const* d_in, const int* in_sizes, int n_in,
                              void* d_out, int out_size) {
    const float* x   = (const float*)d_in[0];
    const float* W1  = (const float*)d_in[1];
    const float* b1  = (const float*)d_in[2];
    const float* W2  = (const float*)d_in[3];
    const float* b2  = (const float*)d_in[4];
    const float* W3  = (const float*)d_in[5];
    const float* b3  = (const float*)d_in[6];
    const float* fw1 = (const float*)d_in[7];
    const float* fb1 = (const float*)d_in[8];
    const float* fw2 = (const float*)d_in[9];
    const float* fb2 = (const float*)d_in[10];
    const int*   ei  = (const int*)d_in[11];
    const int*   bat = (const int*)d_in[12];
    float* out = (float*)d_out;

    float *du, *dz;
    cudaGetSymbolAddress((void**)&du, g_u);
    cudaGetSymbolAddress((void**)&dz, g_z);

    const int SMEM64 = 64 * (FIN + 4) * 4 + 128 * 17 * 8;   // 34816
    const int SMEM128 = 64 * (HH + 4) * 4 + 128 * 17 * 8;   // 51200
    cudaFuncSetAttribute(gemm_kernel<FIN>,
                         cudaFuncAttributeMaxDynamicSharedMemorySize, SMEM64);
    cudaFuncSetAttribute(gemm_kernel<HH>,
                         cudaFuncAttributeMaxDynamicSharedMemorySize, SMEM128);

    // --- CSR build (+ dinv) ---
    init_kernel<<<(NN + 255) / 256, 256>>>();
    hist_kernel<<<(EE + 255) / 256, 256>>>(ei);
    scan1_kernel<<<NBLK, 256>>>();
    scan3_kernel<<<(NN + 255) / 256, 256>>>();
    scatter_kernel<<<(EE + 255) / 256, 256>>>(ei);

    const int GEMM_GRID = (NN + 63) / 64;  // 1563

    // Layer 1
    agg_kernel<FIN><<<(NN * 16 + 255) / 256, 256>>>(x, du);
    gemm_kernel<FIN><<<GEMM_GRID, 256, SMEM64>>>(du, W1, b1, dz);
    // Layer 2
    agg_kernel<HH><<<(NN * 32 + 255) / 256, 256>>>(dz, du);
    gemm_kernel<HH><<<GEMM_GRID, 256, SMEM128>>>(du, W2, b2, dz);
    // Layer 3: aggregation only; GEMM folded into pool_mlp (linearity)
    agg_kernel<HH><<<(NN * 32 + 255) / 256, 256>>>(dz, du);

    pool_mlp_kernel<<<GG, 256>>>(bat, du, W3, b3, fw1, fb1, fw2, fb2, out);
}